// round 1
// baseline (speedup 1.0000x reference)
#include <cuda_runtime.h>
#include <cstdint>

#define D 128
#define HH 256
#define BM 128
#define BK 32
#define NTHREADS 512
#define MAX_NODES 20000

// scratch for segment-sum aggregation (device global: allocation-free)
__device__ float g_agg[MAX_NODES * D];

// ---- smem layout (float offsets) ----
#define AS_ROW 36                    // 128x32 tile, pad to 36 (conflict-free frag reads)
#define AS_BUF (BM * AS_ROW)         // 4608
#define BS_OFF (2 * AS_BUF)          // 9216
#define BS_ROW 264                   // 32x256 tile, pad to 264 (conflict-free)
#define BS_BUF (BK * BS_ROW)         // 8448
#define HS_ROW 260                   // 128x256 relu(h) tile, pad 260 (conflict-free)
#define HS_SIZE (BM * HS_ROW)        // 33280
#define B2_OFF HS_SIZE
#define B2_ROW 136                   // 32x128 tile, pad 136 (conflict-free)
#define B2_BUF (BK * B2_ROW)         // 4352
#define SMEM_FLOATS (B2_OFF + 2 * B2_BUF)   // 41984
#define SMEM_BYTES (SMEM_FLOATS * 4)        // 167936 < 227KB

__device__ __forceinline__ unsigned f2tf(float x) {
    unsigned r;
    asm("cvt.rna.tf32.f32 %0, %1;" : "=r"(r) : "f"(x));
    return r;
}

__device__ __forceinline__ void mma_tf32(float* d, const unsigned* a, const unsigned* b) {
    asm volatile(
        "mma.sync.aligned.m16n8k8.row.col.f32.tf32.tf32.f32 "
        "{%0,%1,%2,%3}, {%4,%5,%6,%7}, {%8,%9}, {%0,%1,%2,%3};\n"
        : "+f"(d[0]), "+f"(d[1]), "+f"(d[2]), "+f"(d[3])
        : "r"(a[0]), "r"(a[1]), "r"(a[2]), "r"(a[3]),
          "r"(b[0]), "r"(b[1]));
}

// Fused 2-layer MLP over BM rows.
//   EDGE=true : A = [ef[e] | nf[src[e]] | nf[dst[e]]]  (K1=384), out=updated_ef,
//               plus red.add scatter of the result into g_agg[dst[e]].
//   EDGE=false: A = [g_agg[n] | nf[n]]                (K1=256), out=updated_nf.
template <int K1, bool EDGE>
__global__ void __launch_bounds__(NTHREADS, 1)
mlp_kernel(const float* __restrict__ nf,
           const float* __restrict__ ef,
           const int* __restrict__ src,
           const int* __restrict__ dst,
           const float* __restrict__ W1,   // [K1][256] row-major
           const float* __restrict__ b1,   // [256]
           const float* __restrict__ W2,   // [256][128] row-major
           const float* __restrict__ b2,   // [128]
           float* __restrict__ out,        // [rows][128]
           int nRows)
{
    extern __shared__ float sm[];
    __shared__ int idx_s[2 * BM];   // [src rows | dst rows] (edge only)

    const int tid  = threadIdx.x;
    const int lane = tid & 31;
    const int warp = tid >> 5;
    const int g    = lane >> 2;     // groupID
    const int tg   = lane & 3;      // threadID_in_group
    const int wm   = warp >> 2;     // 0..3
    const int wn   = warp & 3;      // 0..3
    const int rowBase = blockIdx.x * BM;

    if (EDGE) {
        if (tid < BM) {
            int e = rowBase + tid;
            idx_s[tid] = (e < nRows) ? src[e] : 0;
        } else if (tid < 2 * BM) {
            int e = rowBase + tid - BM;
            idx_s[tid] = (e < nRows) ? dst[e] : 0;
        }
        __syncthreads();
    }

    constexpr int NC1 = K1 / BK;

    float4 rA[2];
    float4 rB[4];

    auto loadA = [&](int k0) {
#pragma unroll
        for (int s = 0; s < 2; ++s) {
            int f4 = tid + s * NTHREADS;
            int r  = f4 >> 3;          // 8 float4 per 32-wide row
            int c  = (f4 & 7) * 4;
            const float* p;
            if (EDGE) {
                if (k0 < D) {
                    int e = rowBase + r; if (e >= nRows) e = nRows - 1;
                    p = ef + (size_t)e * D + (k0 + c);
                } else if (k0 < 2 * D) {
                    p = nf + (size_t)idx_s[r] * D + (k0 - D + c);
                } else {
                    p = nf + (size_t)idx_s[BM + r] * D + (k0 - 2 * D + c);
                }
            } else {
                int rr = rowBase + r; if (rr >= nRows) rr = 0;
                if (k0 < D) p = g_agg + (size_t)rr * D + (k0 + c);
                else        p = nf    + (size_t)rr * D + (k0 - D + c);
            }
            rA[s] = *reinterpret_cast<const float4*>(p);
        }
    };
    auto loadB = [&](int k0) {
#pragma unroll
        for (int s = 0; s < 4; ++s) {
            int f4 = tid + s * NTHREADS;
            int r  = f4 >> 6;          // 64 float4 per 256-wide row
            int c  = (f4 & 63) * 4;
            rB[s] = *reinterpret_cast<const float4*>(W1 + (size_t)(k0 + r) * HH + c);
        }
    };
    auto storeA = [&](int buf) {
        unsigned* As = reinterpret_cast<unsigned*>(sm);
#pragma unroll
        for (int s = 0; s < 2; ++s) {
            int f4 = tid + s * NTHREADS;
            int r  = f4 >> 3;
            int c  = (f4 & 7) * 4;
            uint4 q;
            q.x = f2tf(rA[s].x); q.y = f2tf(rA[s].y);
            q.z = f2tf(rA[s].z); q.w = f2tf(rA[s].w);
            *reinterpret_cast<uint4*>(As + buf * AS_BUF + r * AS_ROW + c) = q;
        }
    };
    auto storeB = [&](int buf) {
        unsigned* Bs = reinterpret_cast<unsigned*>(sm) + BS_OFF;
#pragma unroll
        for (int s = 0; s < 4; ++s) {
            int f4 = tid + s * NTHREADS;
            int r  = f4 >> 6;
            int c  = (f4 & 63) * 4;
            uint4 q;
            q.x = f2tf(rB[s].x); q.y = f2tf(rB[s].y);
            q.z = f2tf(rB[s].z); q.w = f2tf(rB[s].w);
            *reinterpret_cast<uint4*>(Bs + buf * BS_BUF + r * BS_ROW + c) = q;
        }
    };

    // ----- phase 1: acc1[BM,256] = A @ W1 -----
    float acc1[2][8][4];
#pragma unroll
    for (int mi = 0; mi < 2; ++mi)
#pragma unroll
        for (int ni = 0; ni < 8; ++ni)
#pragma unroll
            for (int q = 0; q < 4; ++q) acc1[mi][ni][q] = 0.f;

    loadA(0); loadB(0);
    storeA(0); storeB(0);
    __syncthreads();

    const int m0   = wm * 32;
    const int n0p1 = wn * 64;

    for (int ch = 0; ch < NC1; ++ch) {
        int buf = ch & 1;
        if (ch + 1 < NC1) { loadA((ch + 1) * BK); loadB((ch + 1) * BK); }
        const unsigned* As = reinterpret_cast<const unsigned*>(sm) + buf * AS_BUF;
        const unsigned* Bs = reinterpret_cast<const unsigned*>(sm) + BS_OFF + buf * BS_BUF;
#pragma unroll
        for (int kk = 0; kk < BK / 8; ++kk) {
            int k = kk * 8;
            unsigned a[2][4];
#pragma unroll
            for (int mi = 0; mi < 2; ++mi) {
                int rr = m0 + mi * 16 + g;
                a[mi][0] = As[rr * AS_ROW + k + tg];
                a[mi][1] = As[(rr + 8) * AS_ROW + k + tg];
                a[mi][2] = As[rr * AS_ROW + k + tg + 4];
                a[mi][3] = As[(rr + 8) * AS_ROW + k + tg + 4];
            }
#pragma unroll
            for (int ni = 0; ni < 8; ++ni) {
                unsigned b[2];
                int cc = n0p1 + ni * 8 + g;
                b[0] = Bs[(k + tg) * BS_ROW + cc];
                b[1] = Bs[(k + tg + 4) * BS_ROW + cc];
                mma_tf32(acc1[0][ni], a[0], b);
                mma_tf32(acc1[1][ni], a[1], b);
            }
        }
        if (ch + 1 < NC1) { storeA((ch + 1) & 1); storeB((ch + 1) & 1); __syncthreads(); }
    }

    __syncthreads();   // all warps done with As/Bs before Hs overwrites them

    // epilogue 1: +bias, relu, tf32-convert -> Hs
    {
        unsigned* Hs = reinterpret_cast<unsigned*>(sm);
#pragma unroll
        for (int mi = 0; mi < 2; ++mi) {
#pragma unroll
            for (int ni = 0; ni < 8; ++ni) {
                int cc = n0p1 + ni * 8 + tg * 2;
                float bb0 = __ldg(b1 + cc), bb1 = __ldg(b1 + cc + 1);
                int r0 = m0 + mi * 16 + g;
                float v0 = fmaxf(acc1[mi][ni][0] + bb0, 0.f);
                float v1 = fmaxf(acc1[mi][ni][1] + bb1, 0.f);
                float v2 = fmaxf(acc1[mi][ni][2] + bb0, 0.f);
                float v3 = fmaxf(acc1[mi][ni][3] + bb1, 0.f);
                uint2 q0; q0.x = f2tf(v0); q0.y = f2tf(v1);
                uint2 q1; q1.x = f2tf(v2); q1.y = f2tf(v3);
                *reinterpret_cast<uint2*>(Hs + r0 * HS_ROW + cc) = q0;
                *reinterpret_cast<uint2*>(Hs + (r0 + 8) * HS_ROW + cc) = q1;
            }
        }
    }

    // ----- phase 2: acc2[BM,128] = relu(h) @ W2 -----
    constexpr int NC2 = HH / BK;   // 8
    auto loadB2 = [&](int k0) {
#pragma unroll
        for (int s = 0; s < 2; ++s) {
            int f4 = tid + s * NTHREADS;
            int r  = f4 >> 5;          // 32 float4 per 128-wide row
            int c  = (f4 & 31) * 4;
            rB[s] = *reinterpret_cast<const float4*>(W2 + (size_t)(k0 + r) * D + c);
        }
    };
    auto storeB2 = [&](int buf) {
        unsigned* B2 = reinterpret_cast<unsigned*>(sm) + B2_OFF;
#pragma unroll
        for (int s = 0; s < 2; ++s) {
            int f4 = tid + s * NTHREADS;
            int r  = f4 >> 5;
            int c  = (f4 & 31) * 4;
            uint4 q;
            q.x = f2tf(rB[s].x); q.y = f2tf(rB[s].y);
            q.z = f2tf(rB[s].z); q.w = f2tf(rB[s].w);
            *reinterpret_cast<uint4*>(B2 + buf * B2_BUF + r * B2_ROW + c) = q;
        }
    };

    float acc2[2][4][4] = {};
    loadB2(0);
    storeB2(0);
    __syncthreads();   // Hs + B2 buf0 visible to all warps

    const int n0p2 = wn * 32;
    const unsigned* Hs = reinterpret_cast<const unsigned*>(sm);

    for (int ch = 0; ch < NC2; ++ch) {
        int buf = ch & 1;
        if (ch + 1 < NC2) loadB2((ch + 1) * BK);
        const unsigned* B2 = reinterpret_cast<const unsigned*>(sm) + B2_OFF + buf * B2_BUF;
#pragma unroll
        for (int kk = 0; kk < BK / 8; ++kk) {
            int k  = ch * BK + kk * 8;   // global k into Hs
            int kb = kk * 8;             // within-chunk k for B2
            unsigned a[2][4];
#pragma unroll
            for (int mi = 0; mi < 2; ++mi) {
                int rr = m0 + mi * 16 + g;
                a[mi][0] = Hs[rr * HS_ROW + k + tg];
                a[mi][1] = Hs[(rr + 8) * HS_ROW + k + tg];
                a[mi][2] = Hs[rr * HS_ROW + k + tg + 4];
                a[mi][3] = Hs[(rr + 8) * HS_ROW + k + tg + 4];
            }
#pragma unroll
            for (int ni = 0; ni < 4; ++ni) {
                unsigned b[2];
                int cc = n0p2 + ni * 8 + g;
                b[0] = B2[(kb + tg) * B2_ROW + cc];
                b[1] = B2[(kb + tg + 4) * B2_ROW + cc];
                mma_tf32(acc2[0][ni], a[0], b);
                mma_tf32(acc2[1][ni], a[1], b);
            }
        }
        if (ch + 1 < NC2) { storeB2((ch + 1) & 1); __syncthreads(); }
    }

    // epilogue 2: +bias, store out, scatter-add into g_agg (edge only)
#pragma unroll
    for (int mi = 0; mi < 2; ++mi) {
#pragma unroll
        for (int ni = 0; ni < 4; ++ni) {
            int cc  = n0p2 + ni * 8 + tg * 2;
            float bb0 = __ldg(b2 + cc), bb1 = __ldg(b2 + cc + 1);
            int r0 = m0 + mi * 16 + g;
            int r1 = r0 + 8;
            float v0 = acc2[mi][ni][0] + bb0;
            float v1 = acc2[mi][ni][1] + bb1;
            float v2 = acc2[mi][ni][2] + bb0;
            float v3 = acc2[mi][ni][3] + bb1;
            int gr0 = rowBase + r0, gr1 = rowBase + r1;
            if (gr0 < nRows) {
                *reinterpret_cast<float2*>(out + (size_t)gr0 * D + cc) = make_float2(v0, v1);
                if (EDGE) {
                    float* ap = g_agg + (size_t)idx_s[BM + r0] * D + cc;
                    asm volatile("red.global.add.v2.f32 [%0], {%1,%2};"
                                 :: "l"(ap), "f"(v0), "f"(v1) : "memory");
                }
            }
            if (gr1 < nRows) {
                *reinterpret_cast<float2*>(out + (size_t)gr1 * D + cc) = make_float2(v2, v3);
                if (EDGE) {
                    float* ap = g_agg + (size_t)idx_s[BM + r1] * D + cc;
                    asm volatile("red.global.add.v2.f32 [%0], {%1,%2};"
                                 :: "l"(ap), "f"(v2), "f"(v3) : "memory");
                }
            }
        }
    }
}

__global__ void zero_agg_kernel(int n4) {
    int i = blockIdx.x * blockDim.x + threadIdx.x;
    if (i < n4) {
        reinterpret_cast<float4*>(g_agg)[i] = make_float4(0.f, 0.f, 0.f, 0.f);
    }
}

extern "C" void kernel_launch(void* const* d_in, const int* in_sizes, int n_in,
                              void* d_out, int out_size) {
    const float* nf  = (const float*)d_in[0];
    const float* ef  = (const float*)d_in[1];
    const int*   src = (const int*)d_in[2];
    const int*   dst = (const int*)d_in[3];
    const float* We1 = (const float*)d_in[4];
    const float* be1 = (const float*)d_in[5];
    const float* We2 = (const float*)d_in[6];
    const float* be2 = (const float*)d_in[7];
    const float* Wn1 = (const float*)d_in[8];
    const float* bn1 = (const float*)d_in[9];
    const float* Wn2 = (const float*)d_in[10];
    const float* bn2 = (const float*)d_in[11];

    const int nN = in_sizes[0] / D;   // 20000
    const int nE = in_sizes[2];       // 640000

    float* out_nf = (float*)d_out;                         // [nN, D]
    float* out_ef = (float*)d_out + (size_t)nN * D;        // [nE, D]

    cudaFuncSetAttribute(mlp_kernel<3 * D, true>,
                         cudaFuncAttributeMaxDynamicSharedMemorySize, SMEM_BYTES);
    cudaFuncSetAttribute(mlp_kernel<2 * D, false>,
                         cudaFuncAttributeMaxDynamicSharedMemorySize, SMEM_BYTES);

    // 1) zero the aggregation buffer (must happen every replay)
    int n4 = (nN * D) / 4;
    zero_agg_kernel<<<(n4 + 255) / 256, 256>>>(n4);

    // 2) edge MLP + scatter-add into g_agg
    int gridE = (nE + BM - 1) / BM;
    mlp_kernel<3 * D, true><<<gridE, NTHREADS, SMEM_BYTES>>>(
        nf, ef, src, dst, We1, be1, We2, be2, out_ef, nE);

    // 3) node MLP (reads g_agg)
    int gridN = (nN + BM - 1) / BM;
    mlp_kernel<2 * D, false><<<gridN, NTHREADS, SMEM_BYTES>>>(
        nf, nullptr, nullptr, nullptr, Wn1, bn1, Wn2, bn2, out_nf, nN);
}

// round 10
// speedup vs baseline: 1.1690x; 1.1690x over previous
#include <cuda_runtime.h>
#include <cstdint>

#define D 128
#define HH 256
#define BM 128
#define NTH 256
#define MAX_NODES 20000

__device__ float    g_agg[MAX_NODES * D];
__device__ uint32_t g_W1t_e[HH * 384];   // [n=256][k=384] tf32
__device__ uint32_t g_W2t_e[D * HH];     // [n=128][k=256] tf32
__device__ uint32_t g_W1t_n[HH * HH];    // [n=256][k=256] tf32
__device__ uint32_t g_W2t_n[D * HH];     // [n=128][k=256] tf32

// ---- dynamic smem layout (bytes), all tiles SW128-swizzled, zero padding ----
#define A_OFF 0
#define A_CH  16384                       // 128 rows x 32 tf32
#define B_OFF (2 * A_CH)                  // 32768
#define B_CH  32768                       // 256 rows x 32 tf32 (G2 uses first 16KB)
#define H_OFF (B_OFF + 2 * B_CH)          // 98304
#define SMEM_BYTES (H_OFF + 8 * 16384)    // 229376  (<= 227KB cap)

__device__ __forceinline__ uint32_t f2tf(float x) {
    uint32_t r; asm("cvt.rna.tf32.f32 %0, %1;" : "=r"(r) : "f"(x)); return r;
}
__device__ __forceinline__ uint32_t smem_u32(const void* p) {
    uint32_t a;
    asm("{ .reg .u64 t; cvta.to.shared.u64 t, %1; cvt.u32.u64 %0, t; }" : "=r"(a) : "l"(p));
    return a;
}
__device__ __forceinline__ void cp_async16(uint32_t saddr, const void* g) {
    asm volatile("cp.async.cg.shared.global [%0], [%1], 16;" :: "r"(saddr), "l"(g) : "memory");
}
#define CP_COMMIT() asm volatile("cp.async.commit_group;" ::: "memory")
#define CP_WAIT0()  asm volatile("cp.async.wait_group 0;" ::: "memory")

__device__ __forceinline__ void mma_tf32(float* d, const uint32_t* a, const uint32_t* b) {
    asm volatile(
        "mma.sync.aligned.m16n8k8.row.col.f32.tf32.tf32.f32 "
        "{%0,%1,%2,%3}, {%4,%5,%6,%7}, {%8,%9}, {%0,%1,%2,%3};\n"
        : "+f"(d[0]), "+f"(d[1]), "+f"(d[2]), "+f"(d[3])
        : "r"(a[0]), "r"(a[1]), "r"(a[2]), "r"(a[3]), "r"(b[0]), "r"(b[1]));
}
__device__ __forceinline__ uint32_t sw_off(uint32_t off) {
    return off ^ ((off >> 3) & 0x70);
}

// transpose + tf32-convert all four weight matrices (runs each replay; cheap)
__global__ void convW(const float* __restrict__ We1, const float* __restrict__ We2,
                      const float* __restrict__ Wn1, const float* __restrict__ Wn2) {
    int i = blockIdx.x * 256 + threadIdx.x;
    if (i < 98304) {                       // W1t_e [256][384] <- We1 [384][256]
        int n = i / 384, k = i % 384;
        g_W1t_e[i] = f2tf(We1[(size_t)k * HH + n]);
    } else if (i < 131072) {               // W2t_e [128][256] <- We2 [256][128]
        int j = i - 98304; int n = j / HH, k = j % HH;
        g_W2t_e[j] = f2tf(We2[(size_t)k * D + n]);
    } else if (i < 196608) {               // W1t_n [256][256] <- Wn1 [256][256]
        int j = i - 131072; int n = j / HH, k = j % HH;
        g_W1t_n[j] = f2tf(Wn1[(size_t)k * HH + n]);
    } else if (i < 229376) {               // W2t_n [128][256] <- Wn2 [256][128]
        int j = i - 196608; int n = j / HH, k = j % HH;
        g_W2t_n[j] = f2tf(Wn2[(size_t)k * D + n]);
    }
}

// K1 = 384 (edge) or 256 (node). Fused 2-layer MLP over BM rows.
template <int K1, bool EDGE>
__global__ void __launch_bounds__(NTH, 1)
mpnn(const float* __restrict__ nf,
     const float* __restrict__ ef,
     const int* __restrict__ src,
     const int* __restrict__ dst,
     const float* __restrict__ b1,
     const float* __restrict__ b2,
     float* __restrict__ out,
     int nRows)
{
    extern __shared__ char sm[];
    __shared__ int idx_s[2 * BM];

    const int tid  = threadIdx.x;
    const int wid  = tid >> 5;
    const int lane = tid & 31;
    const int g    = lane >> 2;
    const int tg   = lane & 3;
    const int wm   = wid >> 2;          // 0..1
    const int wn   = wid & 3;           // 0..3
    const int m0   = wm * 64;
    const int n0   = wn * 64;           // GEMM1 (N=256)
    const int n0p2 = wn * 32;           // GEMM2 (N=128)
    const int rowBase = blockIdx.x * BM;
    const uint32_t smbase = smem_u32(sm);
    const uint32_t gx4 = (uint32_t)g << 4;   // swizzle XOR constant (row&7 == g)

    const uint32_t* W1t = EDGE ? g_W1t_e : g_W1t_n;
    const uint32_t* W2t = EDGE ? g_W2t_e : g_W2t_n;

    if (EDGE) {
        if (tid < BM) {
            int e = rowBase + tid;
            idx_s[tid] = (e < nRows) ? src[e] : 0;
        } else {
            int e = rowBase + tid - BM;
            idx_s[tid] = (e < nRows) ? dst[e] : 0;
        }
        __syncthreads();
    }

    constexpr int NC1 = K1 / 32;
    float4 rA[4];

    auto prefetchA = [&](int ch) {
        const int k0 = ch * 32;
#pragma unroll
        for (int s = 0; s < 4; ++s) {
            int f4 = tid + s * NTH;
            int r  = f4 >> 3;
            int c4 = (f4 & 7) * 4;
            if (EDGE) {
                const float* p;
                if (k0 < D)          p = ef + (size_t)(rowBase + r) * D + k0 + c4;
                else if (k0 < 2 * D) p = nf + (size_t)idx_s[r] * D + (k0 - D) + c4;
                else                 p = nf + (size_t)idx_s[BM + r] * D + (k0 - 2 * D) + c4;
                rA[s] = *reinterpret_cast<const float4*>(p);
            } else {
                int gr = rowBase + r;
                bool ok = gr < nRows;
                int rg = ok ? gr : 0;
                if (k0 < D) {
                    float* q = g_agg + (size_t)rg * D + k0 + c4;
                    rA[s] = *reinterpret_cast<const float4*>(q);
                    if (ok) *reinterpret_cast<float4*>(q) = make_float4(0.f, 0.f, 0.f, 0.f);
                } else {
                    rA[s] = *reinterpret_cast<const float4*>(nf + (size_t)rg * D + (k0 - D) + c4);
                }
            }
        }
    };
    auto storeA = [&](int buf) {
        char* base = sm + A_OFF + buf * A_CH;
#pragma unroll
        for (int s = 0; s < 4; ++s) {
            int f4 = tid + s * NTH;
            int r  = f4 >> 3;
            int c4 = (f4 & 7) * 4;
            uint4 q;
            q.x = f2tf(rA[s].x); q.y = f2tf(rA[s].y);
            q.z = f2tf(rA[s].z); q.w = f2tf(rA[s].w);
            *reinterpret_cast<uint4*>(base + sw_off((uint32_t)(r * 128 + c4 * 4))) = q;
        }
    };
    auto cpB1 = [&](int ch, int buf) {
        const int k0 = ch * 32;
        uint32_t dbase = smbase + B_OFF + buf * B_CH;
#pragma unroll
        for (int s = 0; s < 8; ++s) {
            int e = tid + s * NTH;
            int n = e >> 3, kb = e & 7;
            cp_async16(dbase + sw_off((uint32_t)(n * 128 + kb * 16)),
                       W1t + (size_t)n * K1 + k0 + kb * 4);
        }
    };
    auto cpB2 = [&](int ch, int buf) {
        const int k0 = ch * 32;
        uint32_t dbase = smbase + B_OFF + buf * B_CH;
#pragma unroll
        for (int s = 0; s < 4; ++s) {
            int e = tid + s * NTH;
            int n = e >> 3, kb = e & 7;
            cp_async16(dbase + sw_off((uint32_t)(n * 128 + kb * 16)),
                       W2t + (size_t)n * HH + k0 + kb * 4);
        }
    };

    // ================= GEMM1: acc1[128,256] = A @ W1 =================
    float acc1[4][8][4] = {};

    prefetchA(0); storeA(0); cpB1(0, 0); CP_COMMIT(); CP_WAIT0();
    __syncthreads();

    for (int ch = 0; ch < NC1; ++ch) {
        const int b = ch & 1;
        if (ch + 1 < NC1) { prefetchA(ch + 1); cpB1(ch + 1, b ^ 1); CP_COMMIT(); }

        const char* At = sm + A_OFF + b * A_CH;
        const char* Bt = sm + B_OFF + b * B_CH;
#pragma unroll
        for (int kk = 0; kk < 4; ++kk) {
            const int k = kk * 8;
            const uint32_t cX  = ((uint32_t)((k + tg) * 4)) ^ gx4;
            const uint32_t cX4 = ((uint32_t)((k + tg + 4) * 4)) ^ gx4;
            uint32_t a[4][4];
#pragma unroll
            for (int mi = 0; mi < 4; ++mi) {
                int r0 = m0 + mi * 16 + g;
                a[mi][0] = *(const uint32_t*)(At + r0 * 128 + cX);
                a[mi][1] = *(const uint32_t*)(At + (r0 + 8) * 128 + cX);
                a[mi][2] = *(const uint32_t*)(At + r0 * 128 + cX4);
                a[mi][3] = *(const uint32_t*)(At + (r0 + 8) * 128 + cX4);
            }
#pragma unroll
            for (int ni = 0; ni < 8; ++ni) {
                uint32_t bf[2];
                int cc = n0 + ni * 8 + g;
                bf[0] = *(const uint32_t*)(Bt + cc * 128 + cX);
                bf[1] = *(const uint32_t*)(Bt + cc * 128 + cX4);
#pragma unroll
                for (int mi = 0; mi < 4; ++mi) mma_tf32(acc1[mi][ni], a[mi], bf);
            }
        }
        if (ch + 1 < NC1) { storeA(b ^ 1); CP_WAIT0(); }
        __syncthreads();
    }

    // prefetch first GEMM2 weight chunk while epilogue runs
    cpB2(0, 0); CP_COMMIT();

    // ---- epilogue 1: h = relu(acc1 + b1) -> tf32, chunked SW128 tiles ----
#pragma unroll
    for (int mi = 0; mi < 4; ++mi) {
#pragma unroll
        for (int ni = 0; ni < 8; ++ni) {
            int cb = n0 + ni * 8 + tg * 2;
            float bb0 = __ldg(b1 + cb), bb1 = __ldg(b1 + cb + 1);
            int r0 = m0 + mi * 16 + g;
            float v0 = fmaxf(acc1[mi][ni][0] + bb0, 0.f);
            float v1 = fmaxf(acc1[mi][ni][1] + bb1, 0.f);
            float v2 = fmaxf(acc1[mi][ni][2] + bb0, 0.f);
            float v3 = fmaxf(acc1[mi][ni][3] + bb1, 0.f);
            char* Ht = sm + H_OFF + (cb >> 5) * 16384;
            uint32_t colb = (uint32_t)((cb & 31) * 4);
            uint2 q0; q0.x = f2tf(v0); q0.y = f2tf(v1);
            uint2 q1; q1.x = f2tf(v2); q1.y = f2tf(v3);
            *reinterpret_cast<uint2*>(Ht + ((r0 * 128 + colb) ^ gx4)) = q0;
            *reinterpret_cast<uint2*>(Ht + (((r0 + 8) * 128 + colb) ^ gx4)) = q1;
        }
    }
    CP_WAIT0();
    __syncthreads();

    // ================= GEMM2: acc2[128,128] = h @ W2 =================
    float acc2[4][4][4] = {};
    for (int ch = 0; ch < 8; ++ch) {
        const int b = ch & 1;
        if (ch + 1 < 8) { cpB2(ch + 1, b ^ 1); CP_COMMIT(); }

        const char* At = sm + H_OFF + ch * 16384;
        const char* Bt = sm + B_OFF + b * B_CH;
#pragma unroll
        for (int kk = 0; kk < 4; ++kk) {
            const int k = kk * 8;
            const uint32_t cX  = ((uint32_t)((k + tg) * 4)) ^ gx4;
            const uint32_t cX4 = ((uint32_t)((k + tg + 4) * 4)) ^ gx4;
            uint32_t a[4][4];
#pragma unroll
            for (int mi = 0; mi < 4; ++mi) {
                int r0 = m0 + mi * 16 + g;
                a[mi][0] = *(const uint32_t*)(At + r0 * 128 + cX);
                a[mi][1] = *(const uint32_t*)(At + (r0 + 8) * 128 + cX);
                a[mi][2] = *(const uint32_t*)(At + r0 * 128 + cX4);
                a[mi][3] = *(const uint32_t*)(At + (r0 + 8) * 128 + cX4);
            }
#pragma unroll
            for (int ni = 0; ni < 4; ++ni) {
                uint32_t bf[2];
                int cc = n0p2 + ni * 8 + g;
                bf[0] = *(const uint32_t*)(Bt + cc * 128 + cX);
                bf[1] = *(const uint32_t*)(Bt + cc * 128 + cX4);
#pragma unroll
                for (int mi = 0; mi < 4; ++mi) mma_tf32(acc2[mi][ni], a[mi], bf);
            }
        }
        if (ch + 1 < 8) { CP_WAIT0(); }
        __syncthreads();
    }

    // ---- epilogue 2: out = acc2 + b2 (direct), scatter-add (edge) ----
#pragma unroll
    for (int mi = 0; mi < 4; ++mi) {
#pragma unroll
        for (int ni = 0; ni < 4; ++ni) {
            int cc = n0p2 + ni * 8 + tg * 2;
            float bb0 = __ldg(b2 + cc), bb1 = __ldg(b2 + cc + 1);
            int r0 = m0 + mi * 16 + g;
            int r1 = r0 + 8;
            float v0 = acc2[mi][ni][0] + bb0;
            float v1 = acc2[mi][ni][1] + bb1;
            float v2 = acc2[mi][ni][2] + bb0;
            float v3 = acc2[mi][ni][3] + bb1;
            int gr0 = rowBase + r0, gr1 = rowBase + r1;
            if (EDGE || gr0 < nRows) {
                *reinterpret_cast<float2*>(out + (size_t)gr0 * D + cc) = make_float2(v0, v1);
                if (EDGE) {
                    float* ap = g_agg + (size_t)idx_s[BM + r0] * D + cc;
                    asm volatile("red.global.add.v2.f32 [%0], {%1,%2};"
                                 :: "l"(ap), "f"(v0), "f"(v1) : "memory");
                }
            }
            if (EDGE || gr1 < nRows) {
                *reinterpret_cast<float2*>(out + (size_t)gr1 * D + cc) = make_float2(v2, v3);
                if (EDGE) {
                    float* ap = g_agg + (size_t)idx_s[BM + r1] * D + cc;
                    asm volatile("red.global.add.v2.f32 [%0], {%1,%2};"
                                 :: "l"(ap), "f"(v2), "f"(v3) : "memory");
                }
            }
        }
    }
}

extern "C" void kernel_launch(void* const* d_in, const int* in_sizes, int n_in,
                              void* d_out, int out_size) {
    const float* nf  = (const float*)d_in[0];
    const float* ef  = (const float*)d_in[1];
    const int*   src = (const int*)d_in[2];
    const int*   dst = (const int*)d_in[3];
    const float* We1 = (const float*)d_in[4];
    const float* be1 = (const float*)d_in[5];
    const float* We2 = (const float*)d_in[6];
    const float* be2 = (const float*)d_in[7];
    const float* Wn1 = (const float*)d_in[8];
    const float* bn1 = (const float*)d_in[9];
    const float* Wn2 = (const float*)d_in[10];
    const float* bn2 = (const float*)d_in[11];

    const int nN = in_sizes[0] / D;   // 20000
    const int nE = in_sizes[2];       // 640000

    float* out_nf = (float*)d_out;
    float* out_ef = (float*)d_out + (size_t)nN * D;

    cudaFuncSetAttribute(mpnn<3 * D, true>,
                         cudaFuncAttributeMaxDynamicSharedMemorySize, SMEM_BYTES);
    cudaFuncSetAttribute(mpnn<2 * D, false>,
                         cudaFuncAttributeMaxDynamicSharedMemorySize, SMEM_BYTES);

    convW<<<(229376 + 255) / 256, 256>>>(We1, We2, Wn1, Wn2);

    int gridE = (nE + BM - 1) / BM;   // 5000
    mpnn<3 * D, true><<<gridE, NTH, SMEM_BYTES>>>(
        nf, ef, src, dst, be1, be2, out_ef, nE);

    int gridN = (nN + BM - 1) / BM;   // 157
    mpnn<2 * D, false><<<gridN, NTH, SMEM_BYTES>>>(
        nf, nullptr, nullptr, nullptr, bn1, bn2, out_nf, nN);
}

// round 13
// speedup vs baseline: 1.1944x; 1.0217x over previous
#include <cuda_runtime.h>
#include <cstdint>

#define D 128
#define HH 256
#define BM 128
#define NTH 256
#define MAX_NODES 20000

__device__ float    g_agg[MAX_NODES * D];
__device__ uint32_t g_W1t_e[HH * 384];   // [n=256][k=384] tf32
__device__ uint32_t g_W2t_e[D * HH];     // [n=128][k=256] tf32
__device__ uint32_t g_W1t_n[HH * HH];    // [n=256][k=256] tf32
__device__ uint32_t g_W2t_n[D * HH];     // [n=128][k=256] tf32

// ---- dynamic smem layout (bytes), all tiles SW128-swizzled ----
#define A_OFF 0
#define A_CH  16384                       // 128 rows x 32 tf32
#define B_OFF (2 * A_CH)                  // 32768
#define B_CH  32768                       // 256 rows x 32 tf32
#define H_OFF (B_OFF + 2 * B_CH)          // 98304
#define SMEM_BYTES (H_OFF + 8 * 16384)    // 229376

__device__ __forceinline__ uint32_t f2tf(float x) {
    uint32_t r; asm("cvt.rna.tf32.f32 %0, %1;" : "=r"(r) : "f"(x)); return r;
}
__device__ __forceinline__ uint32_t smem_u32(const void* p) {
    uint32_t a;
    asm("{ .reg .u64 t; cvta.to.shared.u64 t, %1; cvt.u32.u64 %0, t; }" : "=r"(a) : "l"(p));
    return a;
}
__device__ __forceinline__ void cp_async16(uint32_t saddr, const void* g) {
    asm volatile("cp.async.cg.shared.global [%0], [%1], 16;" :: "r"(saddr), "l"(g) : "memory");
}
#define CP_COMMIT() asm volatile("cp.async.commit_group;" ::: "memory")
#define CP_WAIT0()  asm volatile("cp.async.wait_group 0;" ::: "memory")

__device__ __forceinline__ void mma_tf32(float* d, const uint32_t* a, const uint32_t* b) {
    asm volatile(
        "mma.sync.aligned.m16n8k8.row.col.f32.tf32.tf32.f32 "
        "{%0,%1,%2,%3}, {%4,%5,%6,%7}, {%8,%9}, {%0,%1,%2,%3};\n"
        : "+f"(d[0]), "+f"(d[1]), "+f"(d[2]), "+f"(d[3])
        : "r"(a[0]), "r"(a[1]), "r"(a[2]), "r"(a[3]), "r"(b[0]), "r"(b[1]));
}
__device__ __forceinline__ void ldsm4(uint32_t* r, uint32_t addr) {
    asm volatile("ldmatrix.sync.aligned.m8n8.x4.shared.b16 {%0,%1,%2,%3}, [%4];"
        : "=r"(r[0]), "=r"(r[1]), "=r"(r[2]), "=r"(r[3]) : "r"(addr));
}
__device__ __forceinline__ uint32_t sw_off(uint32_t off) {
    return off ^ ((off >> 3) & 0x70);
}

// transpose + tf32-convert all four weight matrices (runs each replay; cheap)
__global__ void convW(const float* __restrict__ We1, const float* __restrict__ We2,
                      const float* __restrict__ Wn1, const float* __restrict__ Wn2) {
    int i = blockIdx.x * 256 + threadIdx.x;
    if (i < 98304) {                       // W1t_e [256][384] <- We1 [384][256]
        int n = i / 384, k = i % 384;
        g_W1t_e[i] = f2tf(We1[(size_t)k * HH + n]);
    } else if (i < 131072) {               // W2t_e [128][256] <- We2 [256][128]
        int j = i - 98304; int n = j / HH, k = j % HH;
        g_W2t_e[j] = f2tf(We2[(size_t)k * D + n]);
    } else if (i < 196608) {               // W1t_n [256][256] <- Wn1 [256][256]
        int j = i - 131072; int n = j / HH, k = j % HH;
        g_W1t_n[j] = f2tf(Wn1[(size_t)k * HH + n]);
    } else if (i < 229376) {               // W2t_n [128][256] <- Wn2 [256][128]
        int j = i - 196608; int n = j / HH, k = j % HH;
        g_W2t_n[j] = f2tf(Wn2[(size_t)k * D + n]);
    }
}

// K1 = 384 (edge) or 256 (node). Fused 2-layer MLP over BM rows.
template <int K1, bool EDGE>
__global__ void __launch_bounds__(NTH, 1)
mpnn(const float* __restrict__ nf,
     const float* __restrict__ ef,
     const int* __restrict__ src,
     const int* __restrict__ dst,
     const float* __restrict__ b1,
     const float* __restrict__ b2,
     float* __restrict__ out,
     int nRows)
{
    extern __shared__ char sm[];
    __shared__ int idx_s[2 * BM];

    const int tid  = threadIdx.x;
    const int wid  = tid >> 5;
    const int lane = tid & 31;
    const int g    = lane >> 2;
    const int tg   = lane & 3;
    const int wm   = wid >> 2;          // 0..1
    const int wn   = wid & 3;           // 0..3
    const int m0   = wm * 64;
    const int n0   = wn * 64;           // GEMM1 (N=256)
    const int n0p2 = wn * 32;           // GEMM2 (N=128)
    const int rowBase = blockIdx.x * BM;
    const uint32_t smbase = smem_u32(sm);

    // ldmatrix lane geometry (A-side: matrices {r0-7/klo, r8-15/klo, r0-7/khi, r8-15/khi})
    const int      laneRA = (lane & 7) + ((lane >> 3) & 1) * 8;
    const uint32_t laneKA = ((lane >> 4) & 1) * 16;
    const uint32_t rAx4   = (uint32_t)(laneRA & 7) << 4;
    // B-side: matrices {ni/klo, ni/khi, ni+1/klo, ni+1/khi}
    const int      laneRB = (lane & 7) + ((lane >> 4) & 1) * 8;
    const uint32_t laneKB = ((lane >> 3) & 1) * 16;
    const uint32_t rBx4   = (uint32_t)(lane & 7) << 4;

    const uint32_t* W1t = EDGE ? g_W1t_e : g_W1t_n;
    const uint32_t* W2t = EDGE ? g_W2t_e : g_W2t_n;

    if (EDGE) {
        if (tid < BM) {
            int e = rowBase + tid;
            idx_s[tid] = (e < nRows) ? src[e] : 0;
        } else {
            int e = rowBase + tid - BM;
            idx_s[tid] = (e < nRows) ? dst[e] : 0;
        }
        __syncthreads();
    }

    constexpr int NC1 = K1 / 32;
    float4 rA[4];

    auto prefetchA = [&](int ch) {
        const int k0 = ch * 32;
#pragma unroll
        for (int s = 0; s < 4; ++s) {
            int f4 = tid + s * NTH;
            int r  = f4 >> 3;
            int c4 = (f4 & 7) * 4;
            if (EDGE) {
                const float* p;
                if (k0 < D)          p = ef + (size_t)(rowBase + r) * D + k0 + c4;
                else if (k0 < 2 * D) p = nf + (size_t)idx_s[r] * D + (k0 - D) + c4;
                else                 p = nf + (size_t)idx_s[BM + r] * D + (k0 - 2 * D) + c4;
                rA[s] = *reinterpret_cast<const float4*>(p);
            } else {
                int gr = rowBase + r;
                bool ok = gr < nRows;
                int rg = ok ? gr : 0;
                if (k0 < D) {
                    float* q = g_agg + (size_t)rg * D + k0 + c4;
                    rA[s] = *reinterpret_cast<const float4*>(q);
                    if (ok) *reinterpret_cast<float4*>(q) = make_float4(0.f, 0.f, 0.f, 0.f);
                } else {
                    rA[s] = *reinterpret_cast<const float4*>(nf + (size_t)rg * D + (k0 - D) + c4);
                }
            }
        }
    };
    auto storeA = [&](int buf) {
        char* base = sm + A_OFF + buf * A_CH;
#pragma unroll
        for (int s = 0; s < 4; ++s) {
            int f4 = tid + s * NTH;
            int r  = f4 >> 3;
            int c4 = (f4 & 7) * 4;
            uint4 q;
            q.x = f2tf(rA[s].x); q.y = f2tf(rA[s].y);
            q.z = f2tf(rA[s].z); q.w = f2tf(rA[s].w);
            *reinterpret_cast<uint4*>(base + sw_off((uint32_t)(r * 128 + c4 * 4))) = q;
        }
    };
    auto cpB1 = [&](int ch, int buf) {
        const int k0 = ch * 32;
        uint32_t dbase = smbase + B_OFF + buf * B_CH;
#pragma unroll
        for (int s = 0; s < 8; ++s) {
            int e = tid + s * NTH;
            int n = e >> 3, kb = e & 7;
            cp_async16(dbase + sw_off((uint32_t)(n * 128 + kb * 16)),
                       W1t + (size_t)n * K1 + k0 + kb * 4);
        }
    };
    auto cpB2 = [&](int ch, int buf) {
        const int k0 = ch * 32;
        uint32_t dbase = smbase + B_OFF + buf * B_CH;
#pragma unroll
        for (int s = 0; s < 4; ++s) {
            int e = tid + s * NTH;
            int n = e >> 3, kb = e & 7;
            cp_async16(dbase + sw_off((uint32_t)(n * 128 + kb * 16)),
                       W2t + (size_t)n * HH + k0 + kb * 4);
        }
    };

    // ================= GEMM1: acc1[128,256] = A @ W1 =================
    float acc1[4][8][4] = {};

    prefetchA(0); storeA(0); cpB1(0, 0); CP_COMMIT(); CP_WAIT0();
    __syncthreads();

    for (int ch = 0; ch < NC1; ++ch) {
        const int b = ch & 1;
        if (ch + 1 < NC1) { prefetchA(ch + 1); cpB1(ch + 1, b ^ 1); CP_COMMIT(); }

        const uint32_t aT = smbase + A_OFF + b * A_CH + (uint32_t)((m0 + laneRA) * 128);
        const uint32_t bT = smbase + B_OFF + b * B_CH + (uint32_t)((n0 + laneRB) * 128);
#pragma unroll
        for (int kk = 0; kk < 4; ++kk) {
            const uint32_t koffA = ((uint32_t)(kk * 32) + laneKA) ^ rAx4;
            const uint32_t koffB = ((uint32_t)(kk * 32) + laneKB) ^ rBx4;
            uint32_t a[4][4];
#pragma unroll
            for (int mi = 0; mi < 4; ++mi) ldsm4(a[mi], aT + mi * 2048 + koffA);
#pragma unroll
            for (int np = 0; np < 4; ++np) {
                uint32_t bq[4];
                ldsm4(bq, bT + np * 2048 + koffB);
#pragma unroll
                for (int mi = 0; mi < 4; ++mi) {
                    mma_tf32(acc1[mi][2 * np],     a[mi], bq);
                    mma_tf32(acc1[mi][2 * np + 1], a[mi], bq + 2);
                }
            }
        }
        if (ch + 1 < NC1) { storeA(b ^ 1); CP_WAIT0(); }
        __syncthreads();
    }

    // prefetch first GEMM2 weight chunk while epilogue runs
    cpB2(0, 0); CP_COMMIT();

    // ---- epilogue 1: h = relu(acc1 + b1) -> tf32, chunked SW128 tiles ----
    {
        const uint32_t gx4 = (uint32_t)g << 4;
#pragma unroll
        for (int mi = 0; mi < 4; ++mi) {
#pragma unroll
            for (int ni = 0; ni < 8; ++ni) {
                int cb = n0 + ni * 8 + tg * 2;
                float bb0 = __ldg(b1 + cb), bb1 = __ldg(b1 + cb + 1);
                int r0 = m0 + mi * 16 + g;
                float v0 = fmaxf(acc1[mi][ni][0] + bb0, 0.f);
                float v1 = fmaxf(acc1[mi][ni][1] + bb1, 0.f);
                float v2 = fmaxf(acc1[mi][ni][2] + bb0, 0.f);
                float v3 = fmaxf(acc1[mi][ni][3] + bb1, 0.f);
                char* Ht = sm + H_OFF + (cb >> 5) * 16384;
                uint32_t colb = (uint32_t)((cb & 31) * 4);
                uint2 q0; q0.x = f2tf(v0); q0.y = f2tf(v1);
                uint2 q1; q1.x = f2tf(v2); q1.y = f2tf(v3);
                *reinterpret_cast<uint2*>(Ht + ((r0 * 128 + colb) ^ gx4)) = q0;
                *reinterpret_cast<uint2*>(Ht + (((r0 + 8) * 128 + colb) ^ gx4)) = q1;
            }
        }
    }
    CP_WAIT0();
    __syncthreads();

    // ================= GEMM2: acc2[128,128] = h @ W2 =================
    float acc2[4][4][4] = {};
    for (int ch = 0; ch < 8; ++ch) {
        const int b = ch & 1;
        if (ch + 1 < 8) { cpB2(ch + 1, b ^ 1); CP_COMMIT(); }

        const uint32_t hT = smbase + H_OFF + ch * 16384 + (uint32_t)((m0 + laneRA) * 128);
        const uint32_t bT = smbase + B_OFF + b * B_CH + (uint32_t)((n0p2 + laneRB) * 128);
#pragma unroll
        for (int kk = 0; kk < 4; ++kk) {
            const uint32_t koffA = ((uint32_t)(kk * 32) + laneKA) ^ rAx4;
            const uint32_t koffB = ((uint32_t)(kk * 32) + laneKB) ^ rBx4;
            uint32_t a[4][4];
#pragma unroll
            for (int mi = 0; mi < 4; ++mi) ldsm4(a[mi], hT + mi * 2048 + koffA);
#pragma unroll
            for (int np = 0; np < 2; ++np) {
                uint32_t bq[4];
                ldsm4(bq, bT + np * 2048 + koffB);
#pragma unroll
                for (int mi = 0; mi < 4; ++mi) {
                    mma_tf32(acc2[mi][2 * np],     a[mi], bq);
                    mma_tf32(acc2[mi][2 * np + 1], a[mi], bq + 2);
                }
            }
        }
        if (ch + 1 < 8) { CP_WAIT0(); }
        __syncthreads();
    }

    // ---- epilogue 2: out = acc2 + b2 (direct), scatter-add (edge) ----
#pragma unroll
    for (int mi = 0; mi < 4; ++mi) {
#pragma unroll
        for (int ni = 0; ni < 4; ++ni) {
            int cc = n0p2 + ni * 8 + tg * 2;
            float bb0 = __ldg(b2 + cc), bb1 = __ldg(b2 + cc + 1);
            int r0 = m0 + mi * 16 + g;
            int r1 = r0 + 8;
            float v0 = acc2[mi][ni][0] + bb0;
            float v1 = acc2[mi][ni][1] + bb1;
            float v2 = acc2[mi][ni][2] + bb0;
            float v3 = acc2[mi][ni][3] + bb1;
            int gr0 = rowBase + r0, gr1 = rowBase + r1;
            if (EDGE || gr0 < nRows) {
                *reinterpret_cast<float2*>(out + (size_t)gr0 * D + cc) = make_float2(v0, v1);
                if (EDGE) {
                    float* ap = g_agg + (size_t)idx_s[BM + r0] * D + cc;
                    asm volatile("red.global.add.v2.f32 [%0], {%1,%2};"
                                 :: "l"(ap), "f"(v0), "f"(v1) : "memory");
                }
            }
            if (EDGE || gr1 < nRows) {
                *reinterpret_cast<float2*>(out + (size_t)gr1 * D + cc) = make_float2(v2, v3);
                if (EDGE) {
                    float* ap = g_agg + (size_t)idx_s[BM + r1] * D + cc;
                    asm volatile("red.global.add.v2.f32 [%0], {%1,%2};"
                                 :: "l"(ap), "f"(v2), "f"(v3) : "memory");
                }
            }
        }
    }
}

extern "C" void kernel_launch(void* const* d_in, const int* in_sizes, int n_in,
                              void* d_out, int out_size) {
    const float* nf  = (const float*)d_in[0];
    const float* ef  = (const float*)d_in[1];
    const int*   src = (const int*)d_in[2];
    const int*   dst = (const int*)d_in[3];
    const float* We1 = (const float*)d_in[4];
    const float* be1 = (const float*)d_in[5];
    const float* We2 = (const float*)d_in[6];
    const float* be2 = (const float*)d_in[7];
    const float* Wn1 = (const float*)d_in[8];
    const float* bn1 = (const float*)d_in[9];
    const float* Wn2 = (const float*)d_in[10];
    const float* bn2 = (const float*)d_in[11];

    const int nN = in_sizes[0] / D;   // 20000
    const int nE = in_sizes[2];       // 640000

    float* out_nf = (float*)d_out;
    float* out_ef = (float*)d_out + (size_t)nN * D;

    cudaFuncSetAttribute(mpnn<3 * D, true>,
                         cudaFuncAttributeMaxDynamicSharedMemorySize, SMEM_BYTES);
    cudaFuncSetAttribute(mpnn<2 * D, false>,
                         cudaFuncAttributeMaxDynamicSharedMemorySize, SMEM_BYTES);

    convW<<<(229376 + 255) / 256, 256>>>(We1, We2, Wn1, Wn2);

    int gridE = (nE + BM - 1) / BM;   // 5000
    mpnn<3 * D, true><<<gridE, NTH, SMEM_BYTES>>>(
        nf, ef, src, dst, be1, be2, out_ef, nE);

    int gridN = (nN + BM - 1) / BM;   // 157
    mpnn<2 * D, false><<<gridN, NTH, SMEM_BYTES>>>(
        nf, nullptr, nullptr, nullptr, bn1, bn2, out_nf, nN);
}